// round 1
// baseline (speedup 1.0000x reference)
#include <cuda_runtime.h>
#include <math.h>

#define NB 64
#define NT 4096
#define HE 512
#define HD 512
#define NA 256
#define TCH 8

// Static device scratch (allocation-free per harness rules).
__device__ float g_dec_proj[NB * NA];
__device__ float g_scores[NB * NT];
__device__ float g_ctx_part[NB * TCH * HE];

// ---------------------------------------------------------------------------
// Kernel 1: dec_proj[b][a] = dot(decoder_state[b,:], W_dec[a,:])   (tiny)
// ---------------------------------------------------------------------------
__global__ void k_dec_proj(const float* __restrict__ dec,
                           const float* __restrict__ Wd) {
    int b = blockIdx.x;
    int a = threadIdx.x;  // 256 threads
    const float4* dp = (const float4*)(dec + (size_t)b * HD);
    const float4* wp = (const float4*)(Wd + (size_t)a * HD);
    float s = 0.f;
#pragma unroll 8
    for (int k = 0; k < HD / 4; ++k) {
        float4 d4 = dp[k];
        float4 w4 = wp[k];
        s += d4.x * w4.x + d4.y * w4.y + d4.z * w4.z + d4.w * w4.w;
    }
    g_dec_proj[b * NA + a] = s;
}

// ---------------------------------------------------------------------------
// Kernel 2: fused scores GEMM.
//   For a 64(t) x 256(a) tile: C = enc_tile @ W_enc^T  (K=512),
//   then score[t] = sum_a tanh(C[t][a] + dec_proj[b][a]) * v[a].
// 256 threads, thread microtile 4 rows x 16 cols, K-tile = 32.
// ---------------------------------------------------------------------------
__global__ __launch_bounds__(256, 2)
void k_scores(const float* __restrict__ enc,
              const float* __restrict__ We,
              const float* __restrict__ v) {
    __shared__ float As[64][32];    // enc tile, m-major
    __shared__ float Bs[32][256];   // W_enc tile, k-major (transposed on load)
    __shared__ float red[64][17];   // epilogue reduction

    const int b   = blockIdx.y;
    const int t0  = blockIdx.x * 64;
    const int tid = threadIdx.x;
    const int tx  = tid & 15;   // col group: cols [tx*16, tx*16+16)
    const int ty  = tid >> 4;   // row group: rows [ty*4,  ty*4+4)

    float acc[4][16];
#pragma unroll
    for (int i = 0; i < 4; i++)
#pragma unroll
        for (int j = 0; j < 16; j++) acc[i][j] = 0.f;

    const float* Abase = enc + ((size_t)b * NT + t0) * HE;

    for (int k0 = 0; k0 < HE; k0 += 32) {
        // Load A tile: 64 rows x 32 k-cols = 512 float4, 2 per thread.
#pragma unroll
        for (int l = 0; l < 2; ++l) {
            int q   = tid * 2 + l;        // 0..511
            int row = q >> 3;
            int c4  = q & 7;
            float4 a4 = *(const float4*)(Abase + (size_t)row * HE + k0 + c4 * 4);
            *(float4*)&As[row][c4 * 4] = a4;
        }
        // Load B tile transposed: Bs[kk][a] = W_enc[a][k0+kk]; thread = row a.
        {
            const float* Wrow = We + (size_t)tid * HE + k0;
#pragma unroll
            for (int c4 = 0; c4 < 8; ++c4) {
                float4 w4 = *(const float4*)(Wrow + c4 * 4);
                Bs[c4 * 4 + 0][tid] = w4.x;
                Bs[c4 * 4 + 1][tid] = w4.y;
                Bs[c4 * 4 + 2][tid] = w4.z;
                Bs[c4 * 4 + 3][tid] = w4.w;
            }
        }
        __syncthreads();

#pragma unroll 8
        for (int kk = 0; kk < 32; ++kk) {
            float a_frag[4];
#pragma unroll
            for (int i = 0; i < 4; i++) a_frag[i] = As[ty * 4 + i][kk];
            float b_frag[16];
#pragma unroll
            for (int q = 0; q < 4; q++)
                *(float4*)&b_frag[q * 4] = *(const float4*)&Bs[kk][tx * 16 + q * 4];
#pragma unroll
            for (int i = 0; i < 4; i++)
#pragma unroll
                for (int j = 0; j < 16; j++)
                    acc[i][j] = fmaf(a_frag[i], b_frag[j], acc[i][j]);
        }
        __syncthreads();
    }

    // Epilogue: +dec_proj, tanh, *v, reduce over a.
    float rowsum[4] = {0.f, 0.f, 0.f, 0.f};
#pragma unroll
    for (int j = 0; j < 16; j++) {
        int n = tx * 16 + j;
        float dpv = g_dec_proj[b * NA + n];
        float vv  = v[n];
#pragma unroll
        for (int i = 0; i < 4; i++)
            rowsum[i] += tanhf(acc[i][j] + dpv) * vv;
    }
#pragma unroll
    for (int i = 0; i < 4; i++) red[ty * 4 + i][tx] = rowsum[i];
    __syncthreads();
    if (tid < 64) {
        float s = 0.f;
#pragma unroll
        for (int x = 0; x < 16; x++) s += red[tid][x];
        g_scores[(size_t)b * NT + t0 + tid] = s;
    }
}

// ---------------------------------------------------------------------------
// Kernel 3: softmax over T per batch; writes attn_weights to output.
// ---------------------------------------------------------------------------
__global__ void k_softmax(float* __restrict__ wout) {
    const int b = blockIdx.x;
    const int tid = threadIdx.x;  // 256
    __shared__ float sm[256];
    const float* s = g_scores + (size_t)b * NT;

    float m = -1e30f;
    for (int t = tid; t < NT; t += 256) m = fmaxf(m, s[t]);
    sm[tid] = m;
    __syncthreads();
    for (int off = 128; off > 0; off >>= 1) {
        if (tid < off) sm[tid] = fmaxf(sm[tid], sm[tid + off]);
        __syncthreads();
    }
    m = sm[0];
    __syncthreads();

    float z = 0.f;
    for (int t = tid; t < NT; t += 256) z += expf(s[t] - m);
    sm[tid] = z;
    __syncthreads();
    for (int off = 128; off > 0; off >>= 1) {
        if (tid < off) sm[tid] += sm[tid + off];
        __syncthreads();
    }
    float inv = 1.f / sm[0];

    float* w = wout + (size_t)b * NT;
    for (int t = tid; t < NT; t += 256) w[t] = expf(s[t] - m) * inv;
}

// ---------------------------------------------------------------------------
// Kernel 4: context partial sums over T-chunks (deterministic, no atomics).
// ---------------------------------------------------------------------------
__global__ void k_ctx_part(const float* __restrict__ enc,
                           const float* __restrict__ w) {
    const int b   = blockIdx.x;
    const int tc  = blockIdx.y;
    const int tid = threadIdx.x;  // 256
    const int TLEN = NT / TCH;    // 512
    const float* wp = w + (size_t)b * NT + (size_t)tc * TLEN;
    const float* ep = enc + ((size_t)b * NT + (size_t)tc * TLEN) * HE;
    float a0 = 0.f, a1 = 0.f;
#pragma unroll 4
    for (int t = 0; t < TLEN; ++t) {
        float wt = wp[t];
        a0 = fmaf(wt, ep[(size_t)t * HE + tid],       a0);
        a1 = fmaf(wt, ep[(size_t)t * HE + tid + 256], a1);
    }
    float* dst = g_ctx_part + ((size_t)b * TCH + tc) * HE;
    dst[tid]       = a0;
    dst[tid + 256] = a1;
}

// ---------------------------------------------------------------------------
// Kernel 5: reduce partials -> context output.
// ---------------------------------------------------------------------------
__global__ void k_ctx_reduce(float* __restrict__ ctx) {
    int idx = blockIdx.x * blockDim.x + threadIdx.x;  // over NB*HE
    int b = idx / HE;
    int e = idx % HE;
    float s = 0.f;
#pragma unroll
    for (int c = 0; c < TCH; c++)
        s += g_ctx_part[((size_t)b * TCH + c) * HE + e];
    ctx[idx] = s;
}

// ---------------------------------------------------------------------------
extern "C" void kernel_launch(void* const* d_in, const int* in_sizes, int n_in,
                              void* d_out, int out_size) {
    const float* dec = (const float*)d_in[0];  // (B, H_dec)
    const float* enc = (const float*)d_in[1];  // (B, T, H_enc)
    const float* We  = (const float*)d_in[2];  // (A, H_enc)
    const float* Wd  = (const float*)d_in[3];  // (A, H_dec)
    const float* v   = (const float*)d_in[4];  // (1, A)

    float* out = (float*)d_out;
    float* ctx = out;              // context: B*HE
    float* wts = out + NB * HE;    // attn_weights: B*NT

    k_dec_proj<<<NB, NA>>>(dec, Wd);

    dim3 g2(NT / 64, NB);
    k_scores<<<g2, 256>>>(enc, We, v);

    k_softmax<<<NB, 256>>>(wts);

    dim3 g4(NB, TCH);
    k_ctx_part<<<g4, 256>>>(enc, wts);

    k_ctx_reduce<<<(NB * HE) / 256, 256>>>(ctx);
}

// round 3
// speedup vs baseline: 4.1923x; 4.1923x over previous
#include <cuda_runtime.h>
#include <cuda_bf16.h>
#include <math.h>
#include <stdint.h>

#define NB 64
#define NT 4096
#define HE 512
#define HD 512
#define NA 256
#define TCH 8

// ---- scores GEMM tiling ----
#define BM 128
#define BN 256
#define BK 32
#define NKCH (HE / BK)        // 16
#define THREADS 512

// smem tile sizes (bf16, 80-byte padded rows: 64B data + 16B pad)
#define ROWB 80
#define ASZ (BM * ROWB)       // 10240
#define BSZ (BN * ROWB)       // 20480
#define BUFSZ (2 * ASZ + 2 * BSZ)  // 61440
#define SCAL (2 * BUFSZ)           // 122880
#define SMEM_BYTES (SCAL + 1024 + 1024 + 2048)  // +sdec +sv +srow

// ---------------- static device scratch (allocation-free) ----------------
__device__ float g_dec_proj[NB * NA];
__device__ float g_scores[NB * NT];
__device__ float g_ctx_part[NB * TCH * HE];
// prepacked W_enc bf16 hi/lo: [kchunk 16][var 2][n 256][k 32] (64B rows)
__device__ unsigned char g_Bs[NKCH * 2 * BN * 64];

// ---------------- helpers ----------------
__device__ __forceinline__ unsigned smem_u32(const void* p) {
    unsigned r;
    asm("{ .reg .u64 t; cvta.to.shared.u64 t, %1; cvt.u32.u64 %0, t; }"
        : "=r"(r) : "l"(p));
    return r;
}
__device__ __forceinline__ void cpasync16(unsigned dst, const void* src) {
    asm volatile("cp.async.cg.shared.global [%0], [%1], 16;"
                 :: "r"(dst), "l"(__cvta_generic_to_global(src)) : "memory");
}
__device__ __forceinline__ unsigned pack_bf2(float a, float b) {
    __nv_bfloat162 h = __floats2bfloat162_rn(a, b);
    return *reinterpret_cast<unsigned*>(&h);
}
__device__ __forceinline__ float bflow(float x) {
    __nv_bfloat16 h = __float2bfloat16(x);
    return x - __bfloat162float(h);
}

#define LDSM4(r, addr)                                                        \
    asm volatile("ldmatrix.sync.aligned.m8n8.x4.shared.b16 {%0,%1,%2,%3}, [%4];" \
                 : "=r"((r)[0]), "=r"((r)[1]), "=r"((r)[2]), "=r"((r)[3])     \
                 : "r"(addr))

#define MMA(d, a, b0, b1)                                                     \
    asm volatile(                                                             \
        "mma.sync.aligned.m16n8k16.row.col.f32.bf16.bf16.f32 "                \
        "{%0,%1,%2,%3}, {%4,%5,%6,%7}, {%8,%9}, {%0,%1,%2,%3};"               \
        : "+f"((d)[0]), "+f"((d)[1]), "+f"((d)[2]), "+f"((d)[3])              \
        : "r"((a)[0]), "r"((a)[1]), "r"((a)[2]), "r"((a)[3]), "r"(b0), "r"(b1))

// MUFU-free tanh, abs err ~1e-5 (exp2 via magic-number split + FFMA poly,
// reciprocal via quadratic init + 2 Newton steps).
__device__ __forceinline__ float ftanh(float x) {
    float ax = fminf(fabsf(x), 10.0f);
    float y  = ax * -2.885390082f;            // -2*log2(e)*ax,  y in [-28.9, 0]
    float fn = y + 12582912.0f;               // round-to-nearest-int magic
    int   ni = __float_as_int(fn) - 0x4B400000;
    float f  = y - (fn - 12582912.0f);        // f in [-0.5, 0.5]
    float p  = 1.3371541e-3f;
    p = fmaf(p, f, 9.6181291e-3f);
    p = fmaf(p, f, 5.5504109e-2f);
    p = fmaf(p, f, 2.4022651e-1f);
    p = fmaf(p, f, 6.9314718e-1f);
    p = fmaf(p, f, 1.0f);
    float t = p * __int_as_float((ni + 127) << 23);  // e^{-2ax} in (0,1]
    float d = 1.0f + t;                               // in (1,2]
    float r = fmaf(d, fmaf(d, 0.333333f, -1.5f), 2.166667f);  // ~1/d
    r = r * (2.0f - d * r);
    r = r * (2.0f - d * r);
    float res = fmaf(-2.0f * t, r, 1.0f);
    return copysignf(res, x);
}

// ---------------------------------------------------------------------------
// Kernel 0: prepack W_enc into bf16 hi/lo chunks [c][var][n][k32]
// ---------------------------------------------------------------------------
__global__ void k_wprep(const float* __restrict__ We) {
    int c = blockIdx.x;      // 0..15
    int n = threadIdx.x;     // 0..255
    const float* src = We + (size_t)n * HE + c * BK;
    unsigned hi[8], lo[8];
#pragma unroll
    for (int q = 0; q < 8; q++) {
        float4 f = *(const float4*)(src + q * 4);
        hi[q] = pack_bf2(f.x, f.y) | 0u;
        // pack two 16B-groups: do pairs (x,y) and (z,w) -> need 2 unsigned per 4 floats
        // handled below instead
        (void)f;
    }
    // redo cleanly: 32 floats -> 16 unsigned hi + 16 lo
    unsigned hbuf[16], lbuf[16];
#pragma unroll
    for (int q = 0; q < 8; q++) {
        float4 f = *(const float4*)(src + q * 4);
        hbuf[q * 2 + 0] = pack_bf2(f.x, f.y);
        hbuf[q * 2 + 1] = pack_bf2(f.z, f.w);
        lbuf[q * 2 + 0] = pack_bf2(bflow(f.x), bflow(f.y));
        lbuf[q * 2 + 1] = pack_bf2(bflow(f.z), bflow(f.w));
    }
    unsigned char* dsth = g_Bs + ((size_t)(c * 2 + 0) * BN + n) * 64;
    unsigned char* dstl = g_Bs + ((size_t)(c * 2 + 1) * BN + n) * 64;
#pragma unroll
    for (int q = 0; q < 4; q++) {
        ((uint4*)dsth)[q] = make_uint4(hbuf[q*4], hbuf[q*4+1], hbuf[q*4+2], hbuf[q*4+3]);
        ((uint4*)dstl)[q] = make_uint4(lbuf[q*4], lbuf[q*4+1], lbuf[q*4+2], lbuf[q*4+3]);
    }
    (void)hi; (void)lo;
}

// ---------------------------------------------------------------------------
// Kernel 1: dec_proj
// ---------------------------------------------------------------------------
__global__ void k_dec_proj(const float* __restrict__ dec,
                           const float* __restrict__ Wd) {
    int b = blockIdx.x;
    int a = threadIdx.x;
    const float4* dp = (const float4*)(dec + (size_t)b * HD);
    const float4* wp = (const float4*)(Wd + (size_t)a * HD);
    float s = 0.f;
#pragma unroll 8
    for (int k = 0; k < HD / 4; ++k) {
        float4 d4 = dp[k];
        float4 w4 = wp[k];
        s += d4.x * w4.x + d4.y * w4.y + d4.z * w4.z + d4.w * w4.w;
    }
    g_dec_proj[b * NA + a] = s;
}

// ---------------------------------------------------------------------------
// Kernel 2: fused scores via mma.sync bf16x3 + fast-tanh epilogue
//   grid (NT/128, NB), 512 threads. CTA tile 128(M) x 256(N), K=512.
// ---------------------------------------------------------------------------
__global__ __launch_bounds__(THREADS, 1)
void k_scores(const float* __restrict__ enc, const float* __restrict__ v) {
    extern __shared__ __align__(128) unsigned char smp[];
    const unsigned sb = smem_u32(smp);

    const int tid = threadIdx.x;
    const int wid = tid >> 5;
    const int l   = tid & 31;
    const int wm  = wid & 3;   // 0..3  (M blocks of 32)
    const int wn  = wid >> 2;  // 0..3  (N blocks of 64)
    const int b   = blockIdx.y;
    const int t0  = blockIdx.x * BM;

    // scalars
    float* sdec = (float*)(smp + SCAL);
    float* sv   = (float*)(smp + SCAL + 1024);
    float* srow = (float*)(smp + SCAL + 2048);   // [128][4]
    if (tid < NA) {
        sdec[tid] = g_dec_proj[b * NA + tid];
        sv[tid]   = v[tid];
    }

    const float* Abase = enc + ((size_t)b * NT + t0) * HE;
    const int arow = tid >> 2;   // 0..127
    const int aseg = tid & 3;    // 0..3, 8 floats each

    // ---- loaders ----
    auto ldA = [&](int c, float4& v0, float4& v1) {
        const float* p = Abase + (size_t)arow * HE + c * BK + aseg * 8;
        v0 = *(const float4*)p;
        v1 = *(const float4*)(p + 4);
    };
    auto stA = [&](int buf, float4 v0, float4 v1) {
        unsigned off = buf * BUFSZ + arow * ROWB + aseg * 16;
        uint4 h = make_uint4(pack_bf2(v0.x, v0.y), pack_bf2(v0.z, v0.w),
                             pack_bf2(v1.x, v1.y), pack_bf2(v1.z, v1.w));
        uint4 lo = make_uint4(pack_bf2(bflow(v0.x), bflow(v0.y)),
                              pack_bf2(bflow(v0.z), bflow(v0.w)),
                              pack_bf2(bflow(v1.x), bflow(v1.y)),
                              pack_bf2(bflow(v1.z), bflow(v1.w)));
        *(uint4*)(smp + off)       = h;
        *(uint4*)(smp + off + ASZ) = lo;
    };
    auto ldB = [&](int c, int buf) {
#pragma unroll
        for (int it = 0; it < 4; it++) {
            int i   = tid + it * THREADS;   // 0..2047
            int var = i >> 10;
            int q   = i & 1023;
            int row = q >> 2;
            int cc  = q & 3;
            unsigned dst = sb + buf * BUFSZ + 2 * ASZ + var * BSZ + row * ROWB + cc * 16;
            const unsigned char* src =
                g_Bs + ((size_t)(c * 2 + var) * BN + row) * 64 + cc * 16;
            cpasync16(dst, src);
        }
        asm volatile("cp.async.commit_group;" ::: "memory");
    };

    float acc[2][8][4];
#pragma unroll
    for (int i = 0; i < 2; i++)
#pragma unroll
        for (int j = 0; j < 8; j++)
#pragma unroll
            for (int k = 0; k < 4; k++) acc[i][j][k] = 0.f;

    // ldmatrix lane addressing (constant across loop)
    const unsigned a_lane = (wm * 32 + (l & 15)) * ROWB + ((l >> 4) << 4);
    const unsigned b_lane = (wn * 64 + ((l >> 4) & 1) * 8 + (l & 7)) * ROWB
                          + (((l >> 3) & 1) << 4);

    // prologue: chunk 0 -> buf 0
    {
        float4 v0, v1;
        ldA(0, v0, v1);
        ldB(0, 0);
        stA(0, v0, v1);
        asm volatile("cp.async.wait_group 0;" ::: "memory");
    }
    __syncthreads();

    for (int c = 0; c < NKCH; c++) {
        const int buf = c & 1;
        float4 w0, w1;
        if (c + 1 < NKCH) {
            ldA(c + 1, w0, w1);
            ldB(c + 1, buf ^ 1);
        }

        // ---- compute chunk c ----
        const unsigned sA = sb + buf * BUFSZ;
        const unsigned sB = sb + buf * BUFSZ + 2 * ASZ;
#pragma unroll
        for (int k16 = 0; k16 < 2; k16++) {
            unsigned ah[2][4], al[2][4];
            unsigned aoff = a_lane + k16 * 32;
            LDSM4(ah[0], sA + aoff);
            LDSM4(ah[1], sA + aoff + 16 * ROWB);
            LDSM4(al[0], sA + ASZ + aoff);
            LDSM4(al[1], sA + ASZ + aoff + 16 * ROWB);
            unsigned boff = b_lane + k16 * 32;
#pragma unroll
            for (int np = 0; np < 4; np++) {
                unsigned bh[4], bl[4];
                LDSM4(bh, sB + boff + np * (16 * ROWB));
                LDSM4(bl, sB + BSZ + boff + np * (16 * ROWB));
#pragma unroll
                for (int mt = 0; mt < 2; mt++) {
                    MMA(acc[mt][2 * np],     ah[mt], bh[0], bh[1]);
                    MMA(acc[mt][2 * np],     al[mt], bh[0], bh[1]);
                    MMA(acc[mt][2 * np],     ah[mt], bl[0], bl[1]);
                    MMA(acc[mt][2 * np + 1], ah[mt], bh[2], bh[3]);
                    MMA(acc[mt][2 * np + 1], al[mt], bh[2], bh[3]);
                    MMA(acc[mt][2 * np + 1], ah[mt], bl[2], bl[3]);
                }
            }
        }

        if (c + 1 < NKCH) {
            stA(buf ^ 1, w0, w1);
            asm volatile("cp.async.wait_group 0;" ::: "memory");
        }
        __syncthreads();
    }

    // ---- epilogue: tanh(acc + dec) * v, reduce over 256 cols ----
    const int gid = l >> 2;
    const int tig = l & 3;
    float rs[2][2] = {{0.f, 0.f}, {0.f, 0.f}};
#pragma unroll
    for (int mt = 0; mt < 2; mt++) {
#pragma unroll
        for (int nt = 0; nt < 8; nt++) {
            int col0 = wn * 64 + nt * 8 + tig * 2;
            float d0 = sdec[col0], d1 = sdec[col0 + 1];
            float v0 = sv[col0],   v1 = sv[col0 + 1];
            rs[mt][0] += ftanh(acc[mt][nt][0] + d0) * v0;
            rs[mt][0] += ftanh(acc[mt][nt][1] + d1) * v1;
            rs[mt][1] += ftanh(acc[mt][nt][2] + d0) * v0;
            rs[mt][1] += ftanh(acc[mt][nt][3] + d1) * v1;
        }
    }
#pragma unroll
    for (int mt = 0; mt < 2; mt++)
#pragma unroll
        for (int rh = 0; rh < 2; rh++) {
            float s = rs[mt][rh];
            s += __shfl_xor_sync(0xFFFFFFFFu, s, 1);
            s += __shfl_xor_sync(0xFFFFFFFFu, s, 2);
            if (tig == 0) {
                int row = wm * 32 + mt * 16 + rh * 8 + gid;
                srow[row * 4 + wn] = s;
            }
        }
    __syncthreads();
    if (tid < BM) {
        float s = srow[tid * 4 + 0] + srow[tid * 4 + 1]
                + srow[tid * 4 + 2] + srow[tid * 4 + 3];
        g_scores[(size_t)b * NT + t0 + tid] = s;
    }
}

// ---------------------------------------------------------------------------
// Kernel 3: softmax over T per batch
// ---------------------------------------------------------------------------
__global__ void k_softmax(float* __restrict__ wout) {
    const int b = blockIdx.x;
    const int tid = threadIdx.x;
    __shared__ float sm[256];
    const float* s = g_scores + (size_t)b * NT;

    float m = -1e30f;
    for (int t = tid; t < NT; t += 256) m = fmaxf(m, s[t]);
    sm[tid] = m;
    __syncthreads();
    for (int off = 128; off > 0; off >>= 1) {
        if (tid < off) sm[tid] = fmaxf(sm[tid], sm[tid + off]);
        __syncthreads();
    }
    m = sm[0];
    __syncthreads();

    float z = 0.f;
    for (int t = tid; t < NT; t += 256) z += expf(s[t] - m);
    sm[tid] = z;
    __syncthreads();
    for (int off = 128; off > 0; off >>= 1) {
        if (tid < off) sm[tid] += sm[tid + off];
        __syncthreads();
    }
    float inv = 1.f / sm[0];

    float* w = wout + (size_t)b * NT;
    for (int t = tid; t < NT; t += 256) w[t] = expf(s[t] - m) * inv;
}

// ---------------------------------------------------------------------------
// Kernel 4/5: context
// ---------------------------------------------------------------------------
__global__ void k_ctx_part(const float* __restrict__ enc,
                           const float* __restrict__ w) {
    const int b   = blockIdx.x;
    const int tc  = blockIdx.y;
    const int tid = threadIdx.x;
    const int TLEN = NT / TCH;
    const float* wp = w + (size_t)b * NT + (size_t)tc * TLEN;
    const float* ep = enc + ((size_t)b * NT + (size_t)tc * TLEN) * HE;
    float a0 = 0.f, a1 = 0.f;
#pragma unroll 4
    for (int t = 0; t < TLEN; ++t) {
        float wt = wp[t];
        a0 = fmaf(wt, ep[(size_t)t * HE + tid],       a0);
        a1 = fmaf(wt, ep[(size_t)t * HE + tid + 256], a1);
    }
    float* dst = g_ctx_part + ((size_t)b * TCH + tc) * HE;
    dst[tid]       = a0;
    dst[tid + 256] = a1;
}

__global__ void k_ctx_reduce(float* __restrict__ ctx) {
    int idx = blockIdx.x * blockDim.x + threadIdx.x;
    int b = idx / HE;
    int e = idx % HE;
    float s = 0.f;
#pragma unroll
    for (int c = 0; c < TCH; c++)
        s += g_ctx_part[((size_t)b * TCH + c) * HE + e];
    ctx[idx] = s;
}

// ---------------------------------------------------------------------------
extern "C" void kernel_launch(void* const* d_in, const int* in_sizes, int n_in,
                              void* d_out, int out_size) {
    const float* dec = (const float*)d_in[0];  // (B, H_dec)
    const float* enc = (const float*)d_in[1];  // (B, T, H_enc)
    const float* We  = (const float*)d_in[2];  // (A, H_enc)
    const float* Wd  = (const float*)d_in[3];  // (A, H_dec)
    const float* v   = (const float*)d_in[4];  // (1, A)

    float* out = (float*)d_out;
    float* ctx = out;              // context: B*HE
    float* wts = out + NB * HE;    // attn_weights: B*NT

    cudaFuncSetAttribute(k_scores, cudaFuncAttributeMaxDynamicSharedMemorySize,
                         SMEM_BYTES);

    k_wprep<<<NKCH, BN>>>(We);
    k_dec_proj<<<NB, NA>>>(dec, Wd);

    dim3 g2(NT / BM, NB);
    k_scores<<<g2, THREADS, SMEM_BYTES>>>(enc, v);

    k_softmax<<<NB, 256>>>(wts);

    dim3 g4(NB, TCH);
    k_ctx_part<<<g4, 256>>>(enc, wts);

    k_ctx_reduce<<<(NB * HE) / 256, 256>>>(ctx);
}

// round 4
// speedup vs baseline: 8.6534x; 2.0641x over previous
#include <cuda_runtime.h>
#include <cuda_fp16.h>
#include <math.h>
#include <stdint.h>

#define NB 64
#define NT 4096
#define HE 512
#define HD 512
#define NA 256
#define TCH 16

// ---- scores GEMM tiling ----
#define BM 128
#define BN 256
#define BK 32
#define NKCH (HE / BK)        // 16
#define THREADS 512

// smem tile rows: 64B data + 16B pad = 80B stride
#define ROWB 80
#define ASZ (BM * ROWB)            // 10240 (one variant)
#define BSZ (BN * ROWB)            // 20480 (hi only)
#define BUFSZ (2 * ASZ + BSZ)      // 40960
#define SCAL (2 * BUFSZ)           // 81920
#define SMEM_BYTES (SCAL + 1024 + 1024 + 2048)

// ---------------- static device scratch (allocation-free) ----------------
__device__ float g_dec_proj[NB * NA];
__device__ float g_scores[NB * NT];
__device__ float g_ctx_part[NB * TCH * HE];
// prepacked W_enc fp16 (hi only): [kchunk 16][n 256][k 32] (64B rows)
__device__ unsigned char g_Bs[NKCH * BN * 64];

// ---------------- helpers ----------------
__device__ __forceinline__ unsigned smem_u32(const void* p) {
    unsigned r;
    asm("{ .reg .u64 t; cvta.to.shared.u64 t, %1; cvt.u32.u64 %0, t; }"
        : "=r"(r) : "l"(p));
    return r;
}
__device__ __forceinline__ void cpasync16(unsigned dst, const void* src) {
    asm volatile("cp.async.cg.shared.global [%0], [%1], 16;"
                 :: "r"(dst), "l"(__cvta_generic_to_global(src)) : "memory");
}
__device__ __forceinline__ unsigned pack_h2(float a, float b) {
    __half2 h = __floats2half2_rn(a, b);
    return *reinterpret_cast<unsigned*>(&h);
}
__device__ __forceinline__ float hlow(float x) {
    return x - __half2float(__float2half_rn(x));
}

#define LDSM4(r, addr)                                                        \
    asm volatile("ldmatrix.sync.aligned.m8n8.x4.shared.b16 {%0,%1,%2,%3}, [%4];" \
                 : "=r"((r)[0]), "=r"((r)[1]), "=r"((r)[2]), "=r"((r)[3])     \
                 : "r"(addr))

#define MMA(d, a, b0, b1)                                                     \
    asm volatile(                                                             \
        "mma.sync.aligned.m16n8k16.row.col.f32.f16.f16.f32 "                  \
        "{%0,%1,%2,%3}, {%4,%5,%6,%7}, {%8,%9}, {%0,%1,%2,%3};"               \
        : "+f"((d)[0]), "+f"((d)[1]), "+f"((d)[2]), "+f"((d)[3])              \
        : "r"((a)[0]), "r"((a)[1]), "r"((a)[2]), "r"((a)[3]), "r"(b0), "r"(b1))

// MUFU-free tanh, abs err ~1e-5
__device__ __forceinline__ float ftanh(float x) {
    float ax = fminf(fabsf(x), 10.0f);
    float y  = ax * -2.885390082f;
    float fn = y + 12582912.0f;
    int   ni = __float_as_int(fn) - 0x4B400000;
    float f  = y - (fn - 12582912.0f);
    float p  = 1.3371541e-3f;
    p = fmaf(p, f, 9.6181291e-3f);
    p = fmaf(p, f, 5.5504109e-2f);
    p = fmaf(p, f, 2.4022651e-1f);
    p = fmaf(p, f, 6.9314718e-1f);
    p = fmaf(p, f, 1.0f);
    float t = p * __int_as_float((ni + 127) << 23);
    float d = 1.0f + t;
    float r = fmaf(d, fmaf(d, 0.333333f, -1.5f), 2.166667f);
    r = r * (2.0f - d * r);
    r = r * (2.0f - d * r);
    float res = fmaf(-2.0f * t, r, 1.0f);
    return copysignf(res, x);
}

// ---------------------------------------------------------------------------
// Kernel 0: prepack W_enc fp16 hi chunks [c][n][k32]
// ---------------------------------------------------------------------------
__global__ void k_wprep(const float* __restrict__ We) {
    int c = blockIdx.x;      // 0..15
    int n = threadIdx.x;     // 0..255
    const float* src = We + (size_t)n * HE + c * BK;
    unsigned hbuf[16];
#pragma unroll
    for (int q = 0; q < 8; q++) {
        float4 f = *(const float4*)(src + q * 4);
        hbuf[q * 2 + 0] = pack_h2(f.x, f.y);
        hbuf[q * 2 + 1] = pack_h2(f.z, f.w);
    }
    unsigned char* dsth = g_Bs + ((size_t)c * BN + n) * 64;
#pragma unroll
    for (int q = 0; q < 4; q++)
        ((uint4*)dsth)[q] = make_uint4(hbuf[q*4], hbuf[q*4+1], hbuf[q*4+2], hbuf[q*4+3]);
}

// ---------------------------------------------------------------------------
// Kernel 1: dec_proj
// ---------------------------------------------------------------------------
__global__ void k_dec_proj(const float* __restrict__ dec,
                           const float* __restrict__ Wd) {
    int b = blockIdx.x;
    int a = threadIdx.x;
    const float4* dp = (const float4*)(dec + (size_t)b * HD);
    const float4* wp = (const float4*)(Wd + (size_t)a * HD);
    float s = 0.f;
#pragma unroll 8
    for (int k = 0; k < HD / 4; ++k) {
        float4 d4 = dp[k];
        float4 w4 = wp[k];
        s += d4.x * w4.x + d4.y * w4.y + d4.z * w4.z + d4.w * w4.w;
    }
    g_dec_proj[b * NA + a] = s;
}

// ---------------------------------------------------------------------------
// Kernel 2: fused scores via mma.sync fp16x2 + fast-tanh epilogue
//   grid (NT/128, NB), 512 threads. CTA tile 128(M) x 256(N), K=512.
//   A split hi+lo fp16 (exact x = xh + xl to fp16 rounding), B hi only:
//   (ah+al)·bh = a·bh  -> error only from bl, ~2^-11 relative.
// ---------------------------------------------------------------------------
__global__ __launch_bounds__(THREADS, 1)
void k_scores(const float* __restrict__ enc, const float* __restrict__ v) {
    extern __shared__ __align__(128) unsigned char smp[];
    const unsigned sb = smem_u32(smp);

    const int tid = threadIdx.x;
    const int wid = tid >> 5;
    const int l   = tid & 31;
    const int wm  = wid & 3;   // M blocks of 32
    const int wn  = wid >> 2;  // N blocks of 64
    const int b   = blockIdx.y;
    const int t0  = blockIdx.x * BM;

    float* sdec = (float*)(smp + SCAL);
    float* sv   = (float*)(smp + SCAL + 1024);
    float* srow = (float*)(smp + SCAL + 2048);   // [128][4]
    if (tid < NA) {
        sdec[tid] = g_dec_proj[b * NA + tid];
        sv[tid]   = v[tid];
    }

    const float* Abase = enc + ((size_t)b * NT + t0) * HE;
    const int arow = tid >> 2;   // 0..127
    const int aseg = tid & 3;    // 8 floats each

    auto ldA = [&](int c, float4& v0, float4& v1) {
        const float* p = Abase + (size_t)arow * HE + c * BK + aseg * 8;
        v0 = *(const float4*)p;
        v1 = *(const float4*)(p + 4);
    };
    auto stA = [&](int buf, float4 v0, float4 v1) {
        unsigned off = buf * BUFSZ + arow * ROWB + aseg * 16;
        uint4 h = make_uint4(pack_h2(v0.x, v0.y), pack_h2(v0.z, v0.w),
                             pack_h2(v1.x, v1.y), pack_h2(v1.z, v1.w));
        uint4 lo = make_uint4(pack_h2(hlow(v0.x), hlow(v0.y)),
                              pack_h2(hlow(v0.z), hlow(v0.w)),
                              pack_h2(hlow(v1.x), hlow(v1.y)),
                              pack_h2(hlow(v1.z), hlow(v1.w)));
        *(uint4*)(smp + off)       = h;
        *(uint4*)(smp + off + ASZ) = lo;
    };
    auto ldB = [&](int c, int buf) {
#pragma unroll
        for (int it = 0; it < 2; it++) {
            int i   = tid + it * THREADS;   // 0..1023
            int row = i >> 2;
            int cc  = i & 3;
            unsigned dst = sb + buf * BUFSZ + 2 * ASZ + row * ROWB + cc * 16;
            const unsigned char* src = g_Bs + ((size_t)c * BN + row) * 64 + cc * 16;
            cpasync16(dst, src);
        }
        asm volatile("cp.async.commit_group;" ::: "memory");
    };

    float acc[2][8][4];
#pragma unroll
    for (int i = 0; i < 2; i++)
#pragma unroll
        for (int j = 0; j < 8; j++)
#pragma unroll
            for (int k = 0; k < 4; k++) acc[i][j][k] = 0.f;

    const unsigned a_lane = (wm * 32 + (l & 15)) * ROWB + ((l >> 4) << 4);
    const unsigned b_lane = (wn * 64 + ((l >> 4) & 1) * 8 + (l & 7)) * ROWB
                          + (((l >> 3) & 1) << 4);

    // prologue
    {
        float4 v0, v1;
        ldA(0, v0, v1);
        ldB(0, 0);
        stA(0, v0, v1);
        asm volatile("cp.async.wait_group 0;" ::: "memory");
    }
    __syncthreads();

    for (int c = 0; c < NKCH; c++) {
        const int buf = c & 1;
        float4 w0, w1;
        if (c + 1 < NKCH) {
            ldA(c + 1, w0, w1);
            ldB(c + 1, buf ^ 1);
        }

        const unsigned sA = sb + buf * BUFSZ;
        const unsigned sB = sb + buf * BUFSZ + 2 * ASZ;
#pragma unroll
        for (int k16 = 0; k16 < 2; k16++) {
            unsigned ah[2][4], al[2][4];
            unsigned aoff = a_lane + k16 * 32;
            LDSM4(ah[0], sA + aoff);
            LDSM4(ah[1], sA + aoff + 16 * ROWB);
            LDSM4(al[0], sA + ASZ + aoff);
            LDSM4(al[1], sA + ASZ + aoff + 16 * ROWB);
            unsigned boff = b_lane + k16 * 32;
#pragma unroll
            for (int np = 0; np < 4; np++) {
                unsigned bh[4];
                LDSM4(bh, sB + boff + np * (16 * ROWB));
#pragma unroll
                for (int mt = 0; mt < 2; mt++) {
                    MMA(acc[mt][2 * np],     ah[mt], bh[0], bh[1]);
                    MMA(acc[mt][2 * np],     al[mt], bh[0], bh[1]);
                    MMA(acc[mt][2 * np + 1], ah[mt], bh[2], bh[3]);
                    MMA(acc[mt][2 * np + 1], al[mt], bh[2], bh[3]);
                }
            }
        }

        if (c + 1 < NKCH) {
            stA(buf ^ 1, w0, w1);
            asm volatile("cp.async.wait_group 0;" ::: "memory");
        }
        __syncthreads();
    }

    // epilogue: tanh(acc + dec) * v, reduce over 256 cols
    const int gid = l >> 2;
    const int tig = l & 3;
    float rs[2][2] = {{0.f, 0.f}, {0.f, 0.f}};
#pragma unroll
    for (int mt = 0; mt < 2; mt++) {
#pragma unroll
        for (int nt = 0; nt < 8; nt++) {
            int col0 = wn * 64 + nt * 8 + tig * 2;
            float d0 = sdec[col0], d1 = sdec[col0 + 1];
            float v0 = sv[col0],   v1 = sv[col0 + 1];
            rs[mt][0] += ftanh(acc[mt][nt][0] + d0) * v0;
            rs[mt][0] += ftanh(acc[mt][nt][1] + d1) * v1;
            rs[mt][1] += ftanh(acc[mt][nt][2] + d0) * v0;
            rs[mt][1] += ftanh(acc[mt][nt][3] + d1) * v1;
        }
    }
#pragma unroll
    for (int mt = 0; mt < 2; mt++)
#pragma unroll
        for (int rh = 0; rh < 2; rh++) {
            float s = rs[mt][rh];
            s += __shfl_xor_sync(0xFFFFFFFFu, s, 1);
            s += __shfl_xor_sync(0xFFFFFFFFu, s, 2);
            if (tig == 0) {
                int row = wm * 32 + mt * 16 + rh * 8 + gid;
                srow[row * 4 + wn] = s;
            }
        }
    __syncthreads();
    if (tid < BM) {
        float s = srow[tid * 4 + 0] + srow[tid * 4 + 1]
                + srow[tid * 4 + 2] + srow[tid * 4 + 3];
        g_scores[(size_t)b * NT + t0 + tid] = s;
    }
}

// ---------------------------------------------------------------------------
// Kernel 3: softmax over T per batch
// ---------------------------------------------------------------------------
__global__ void k_softmax(float* __restrict__ wout) {
    const int b = blockIdx.x;
    const int tid = threadIdx.x;
    __shared__ float sm[256];
    const float* s = g_scores + (size_t)b * NT;

    float m = -1e30f;
    for (int t = tid; t < NT; t += 256) m = fmaxf(m, s[t]);
    sm[tid] = m;
    __syncthreads();
    for (int off = 128; off > 0; off >>= 1) {
        if (tid < off) sm[tid] = fmaxf(sm[tid], sm[tid + off]);
        __syncthreads();
    }
    m = sm[0];
    __syncthreads();

    float z = 0.f;
    for (int t = tid; t < NT; t += 256) z += expf(s[t] - m);
    sm[tid] = z;
    __syncthreads();
    for (int off = 128; off > 0; off >>= 1) {
        if (tid < off) sm[tid] += sm[tid + off];
        __syncthreads();
    }
    float inv = 1.f / sm[0];

    float* w = wout + (size_t)b * NT;
    for (int t = tid; t < NT; t += 256) w[t] = expf(s[t] - m) * inv;
}

// ---------------------------------------------------------------------------
// Kernel 4/5: context
// ---------------------------------------------------------------------------
__global__ void k_ctx_part(const float* __restrict__ enc,
                           const float* __restrict__ w) {
    const int b   = blockIdx.x;
    const int tc  = blockIdx.y;
    const int tid = threadIdx.x;
    const int TLEN = NT / TCH;   // 256
    const float* wp = w + (size_t)b * NT + (size_t)tc * TLEN;
    const float* ep = enc + ((size_t)b * NT + (size_t)tc * TLEN) * HE;
    float a0 = 0.f, a1 = 0.f;
#pragma unroll 4
    for (int t = 0; t < TLEN; ++t) {
        float wt = wp[t];
        a0 = fmaf(wt, ep[(size_t)t * HE + tid],       a0);
        a1 = fmaf(wt, ep[(size_t)t * HE + tid + 256], a1);
    }
    float* dst = g_ctx_part + ((size_t)b * TCH + tc) * HE;
    dst[tid]       = a0;
    dst[tid + 256] = a1;
}

__global__ void k_ctx_reduce(float* __restrict__ ctx) {
    int idx = blockIdx.x * blockDim.x + threadIdx.x;
    int b = idx / HE;
    int e = idx % HE;
    float s = 0.f;
#pragma unroll
    for (int c = 0; c < TCH; c++)
        s += g_ctx_part[((size_t)b * TCH + c) * HE + e];
    ctx[idx] = s;
}

// ---------------------------------------------------------------------------
extern "C" void kernel_launch(void* const* d_in, const int* in_sizes, int n_in,
                              void* d_out, int out_size) {
    const float* dec = (const float*)d_in[0];  // (B, H_dec)
    const float* enc = (const float*)d_in[1];  // (B, T, H_enc)
    const float* We  = (const float*)d_in[2];  // (A, H_enc)
    const float* Wd  = (const float*)d_in[3];  // (A, H_dec)
    const float* v   = (const float*)d_in[4];  // (1, A)

    float* out = (float*)d_out;
    float* ctx = out;              // context: B*HE
    float* wts = out + NB * HE;    // attn_weights: B*NT

    cudaFuncSetAttribute(k_scores, cudaFuncAttributeMaxDynamicSharedMemorySize,
                         SMEM_BYTES);

    k_wprep<<<NKCH, BN>>>(We);
    k_dec_proj<<<NB, NA>>>(dec, Wd);

    dim3 g2(NT / BM, NB);
    k_scores<<<g2, THREADS, SMEM_BYTES>>>(enc, v);

    k_softmax<<<NB, 256>>>(wts);

    dim3 g4(NB, TCH);
    k_ctx_part<<<g4, 256>>>(enc, wts);

    k_ctx_reduce<<<(NB * HE) / 256, 256>>>(ctx);
}

// round 5
// speedup vs baseline: 11.7667x; 1.3598x over previous
#include <cuda_runtime.h>
#include <cuda_fp16.h>
#include <math.h>
#include <stdint.h>

#define NB 64
#define NT 4096
#define HE 512
#define HD 512
#define NA 256
#define TCH 32

// ---- scores GEMM tiling ----
#define BM 128
#define BN 256
#define BK 32
#define NKCH (HE / BK)        // 16
#define THREADS 512

// smem tile rows: 64B data + 16B pad = 80B stride
#define ROWB 80
#define ASZ (BM * ROWB)            // 10240 (hi only)
#define BSZ (BN * ROWB)            // 20480 (hi only)
#define BUFSZ (ASZ + BSZ)          // 30720
#define SCAL (2 * BUFSZ)           // 61440
#define SMEM_BYTES (SCAL + 1024 + 1024 + 2048)

// ---------------- static device scratch (allocation-free) ----------------
__device__ float g_dec_proj[NB * NA];
__device__ float g_scores[NB * NT];
__device__ float g_ctx_part[NB * TCH * HE];
// prepacked W_enc fp16: [kchunk 16][n 256][k 32] (64B rows)
__device__ unsigned char g_Bs[NKCH * BN * 64];

// ---------------- helpers ----------------
__device__ __forceinline__ unsigned smem_u32(const void* p) {
    unsigned r;
    asm("{ .reg .u64 t; cvta.to.shared.u64 t, %1; cvt.u32.u64 %0, t; }"
        : "=r"(r) : "l"(p));
    return r;
}
__device__ __forceinline__ void cpasync16(unsigned dst, const void* src) {
    asm volatile("cp.async.cg.shared.global [%0], [%1], 16;"
                 :: "r"(dst), "l"(__cvta_generic_to_global(src)) : "memory");
}
__device__ __forceinline__ unsigned pack_h2(float a, float b) {
    __half2 h = __floats2half2_rn(a, b);
    return *reinterpret_cast<unsigned*>(&h);
}

#define LDSM4(r, addr)                                                        \
    asm volatile("ldmatrix.sync.aligned.m8n8.x4.shared.b16 {%0,%1,%2,%3}, [%4];" \
                 : "=r"((r)[0]), "=r"((r)[1]), "=r"((r)[2]), "=r"((r)[3])     \
                 : "r"(addr))

#define MMA(d, a, b0, b1)                                                     \
    asm volatile(                                                             \
        "mma.sync.aligned.m16n8k16.row.col.f32.f16.f16.f32 "                  \
        "{%0,%1,%2,%3}, {%4,%5,%6,%7}, {%8,%9}, {%0,%1,%2,%3};"               \
        : "+f"((d)[0]), "+f"((d)[1]), "+f"((d)[2]), "+f"((d)[3])              \
        : "r"((a)[0]), "r"((a)[1]), "r"((a)[2]), "r"((a)[3]), "r"(b0), "r"(b1))

// MUFU-free tanh, abs err ~1e-5
__device__ __forceinline__ float ftanh(float x) {
    float ax = fminf(fabsf(x), 10.0f);
    float y  = ax * -2.885390082f;
    float fn = y + 12582912.0f;
    int   ni = __float_as_int(fn) - 0x4B400000;
    float f  = y - (fn - 12582912.0f);
    float p  = 1.3371541e-3f;
    p = fmaf(p, f, 9.6181291e-3f);
    p = fmaf(p, f, 5.5504109e-2f);
    p = fmaf(p, f, 2.4022651e-1f);
    p = fmaf(p, f, 6.9314718e-1f);
    p = fmaf(p, f, 1.0f);
    float t = p * __int_as_float((ni + 127) << 23);
    float d = 1.0f + t;
    float r = fmaf(d, fmaf(d, 0.333333f, -1.5f), 2.166667f);
    r = r * (2.0f - d * r);
    r = r * (2.0f - d * r);
    float res = fmaf(-2.0f * t, r, 1.0f);
    return copysignf(res, x);
}

// ---------------------------------------------------------------------------
// Kernel 0: prepack W_enc fp16 chunks [c][n][k32]
// ---------------------------------------------------------------------------
__global__ void k_wprep(const float* __restrict__ We) {
    int c = blockIdx.x;      // 0..15
    int n = threadIdx.x;     // 0..255
    const float* src = We + (size_t)n * HE + c * BK;
    unsigned hbuf[16];
#pragma unroll
    for (int q = 0; q < 8; q++) {
        float4 f = *(const float4*)(src + q * 4);
        hbuf[q * 2 + 0] = pack_h2(f.x, f.y);
        hbuf[q * 2 + 1] = pack_h2(f.z, f.w);
    }
    unsigned char* dsth = g_Bs + ((size_t)c * BN + n) * 64;
#pragma unroll
    for (int q = 0; q < 4; q++)
        ((uint4*)dsth)[q] = make_uint4(hbuf[q*4], hbuf[q*4+1], hbuf[q*4+2], hbuf[q*4+3]);
}

// ---------------------------------------------------------------------------
// Kernel 1: dec_proj
// ---------------------------------------------------------------------------
__global__ void k_dec_proj(const float* __restrict__ dec,
                           const float* __restrict__ Wd) {
    int b = blockIdx.x;
    int a = threadIdx.x;
    const float4* dp = (const float4*)(dec + (size_t)b * HD);
    const float4* wp = (const float4*)(Wd + (size_t)a * HD);
    float s = 0.f;
#pragma unroll 8
    for (int k = 0; k < HD / 4; ++k) {
        float4 d4 = dp[k];
        float4 w4 = wp[k];
        s += d4.x * w4.x + d4.y * w4.y + d4.z * w4.z + d4.w * w4.w;
    }
    g_dec_proj[b * NA + a] = s;
}

// ---------------------------------------------------------------------------
// Kernel 2: fused scores via mma.sync fp16 single product + fast-tanh epilogue
//   grid (NT/128, NB), 512 threads. CTA tile 128(M) x 256(N), K=512.
// ---------------------------------------------------------------------------
__global__ __launch_bounds__(THREADS, 1)
void k_scores(const float* __restrict__ enc, const float* __restrict__ v) {
    extern __shared__ __align__(128) unsigned char smp[];
    const unsigned sb = smem_u32(smp);

    const int tid = threadIdx.x;
    const int wid = tid >> 5;
    const int l   = tid & 31;
    const int wm  = wid & 3;   // M blocks of 32
    const int wn  = wid >> 2;  // N blocks of 64
    const int b   = blockIdx.y;
    const int t0  = blockIdx.x * BM;

    float* sdec = (float*)(smp + SCAL);
    float* sv   = (float*)(smp + SCAL + 1024);
    float* srow = (float*)(smp + SCAL + 2048);   // [128][4]
    if (tid < NA) {
        sdec[tid] = g_dec_proj[b * NA + tid];
        sv[tid]   = v[tid];
    }

    const float* Abase = enc + ((size_t)b * NT + t0) * HE;
    const int arow = tid >> 2;   // 0..127
    const int aseg = tid & 3;    // 8 floats each

    auto ldA = [&](int c, float4& v0, float4& v1) {
        const float* p = Abase + (size_t)arow * HE + c * BK + aseg * 8;
        v0 = *(const float4*)p;
        v1 = *(const float4*)(p + 4);
    };
    auto stA = [&](int buf, float4 v0, float4 v1) {
        unsigned off = buf * BUFSZ + arow * ROWB + aseg * 16;
        uint4 h = make_uint4(pack_h2(v0.x, v0.y), pack_h2(v0.z, v0.w),
                             pack_h2(v1.x, v1.y), pack_h2(v1.z, v1.w));
        *(uint4*)(smp + off) = h;
    };
    auto ldB = [&](int c, int buf) {
#pragma unroll
        for (int it = 0; it < 2; it++) {
            int i   = tid + it * THREADS;   // 0..1023
            int row = i >> 2;
            int cc  = i & 3;
            unsigned dst = sb + buf * BUFSZ + ASZ + row * ROWB + cc * 16;
            const unsigned char* src = g_Bs + ((size_t)c * BN + row) * 64 + cc * 16;
            cpasync16(dst, src);
        }
        asm volatile("cp.async.commit_group;" ::: "memory");
    };

    float acc[2][8][4];
#pragma unroll
    for (int i = 0; i < 2; i++)
#pragma unroll
        for (int j = 0; j < 8; j++)
#pragma unroll
            for (int k = 0; k < 4; k++) acc[i][j][k] = 0.f;

    const unsigned a_lane = (wm * 32 + (l & 15)) * ROWB + ((l >> 4) << 4);
    const unsigned b_lane = (wn * 64 + ((l >> 4) & 1) * 8 + (l & 7)) * ROWB
                          + (((l >> 3) & 1) << 4);

    // prologue
    {
        float4 v0, v1;
        ldA(0, v0, v1);
        ldB(0, 0);
        stA(0, v0, v1);
        asm volatile("cp.async.wait_group 0;" ::: "memory");
    }
    __syncthreads();

    for (int c = 0; c < NKCH; c++) {
        const int buf = c & 1;
        float4 w0, w1;
        if (c + 1 < NKCH) {
            ldA(c + 1, w0, w1);
            ldB(c + 1, buf ^ 1);
        }

        const unsigned sA = sb + buf * BUFSZ;
        const unsigned sB = sb + buf * BUFSZ + ASZ;
#pragma unroll
        for (int k16 = 0; k16 < 2; k16++) {
            unsigned ah[2][4];
            unsigned aoff = a_lane + k16 * 32;
            LDSM4(ah[0], sA + aoff);
            LDSM4(ah[1], sA + aoff + 16 * ROWB);
            unsigned boff = b_lane + k16 * 32;
#pragma unroll
            for (int np = 0; np < 4; np++) {
                unsigned bh[4];
                LDSM4(bh, sB + boff + np * (16 * ROWB));
#pragma unroll
                for (int mt = 0; mt < 2; mt++) {
                    MMA(acc[mt][2 * np],     ah[mt], bh[0], bh[1]);
                    MMA(acc[mt][2 * np + 1], ah[mt], bh[2], bh[3]);
                }
            }
        }

        if (c + 1 < NKCH) {
            stA(buf ^ 1, w0, w1);
            asm volatile("cp.async.wait_group 0;" ::: "memory");
        }
        __syncthreads();
    }

    // epilogue: tanh(acc + dec) * v, reduce over 256 cols
    const int gid = l >> 2;
    const int tig = l & 3;
    float rs[2][2] = {{0.f, 0.f}, {0.f, 0.f}};
#pragma unroll
    for (int mt = 0; mt < 2; mt++) {
#pragma unroll
        for (int nt = 0; nt < 8; nt++) {
            int col0 = wn * 64 + nt * 8 + tig * 2;
            float d0 = sdec[col0], d1 = sdec[col0 + 1];
            float v0 = sv[col0],   v1 = sv[col0 + 1];
            rs[mt][0] += ftanh(acc[mt][nt][0] + d0) * v0;
            rs[mt][0] += ftanh(acc[mt][nt][1] + d1) * v1;
            rs[mt][1] += ftanh(acc[mt][nt][2] + d0) * v0;
            rs[mt][1] += ftanh(acc[mt][nt][3] + d1) * v1;
        }
    }
#pragma unroll
    for (int mt = 0; mt < 2; mt++)
#pragma unroll
        for (int rh = 0; rh < 2; rh++) {
            float s = rs[mt][rh];
            s += __shfl_xor_sync(0xFFFFFFFFu, s, 1);
            s += __shfl_xor_sync(0xFFFFFFFFu, s, 2);
            if (tig == 0) {
                int row = wm * 32 + mt * 16 + rh * 8 + gid;
                srow[row * 4 + wn] = s;
            }
        }
    __syncthreads();
    if (tid < BM) {
        float s = srow[tid * 4 + 0] + srow[tid * 4 + 1]
                + srow[tid * 4 + 2] + srow[tid * 4 + 3];
        g_scores[(size_t)b * NT + t0 + tid] = s;
    }
}

// ---------------------------------------------------------------------------
// Kernel 3: softmax over T per batch
// ---------------------------------------------------------------------------
__global__ void k_softmax(float* __restrict__ wout) {
    const int b = blockIdx.x;
    const int tid = threadIdx.x;
    __shared__ float sm[256];
    const float* s = g_scores + (size_t)b * NT;

    float m = -1e30f;
    for (int t = tid; t < NT; t += 256) m = fmaxf(m, s[t]);
    sm[tid] = m;
    __syncthreads();
    for (int off = 128; off > 0; off >>= 1) {
        if (tid < off) sm[tid] = fmaxf(sm[tid], sm[tid + off]);
        __syncthreads();
    }
    m = sm[0];
    __syncthreads();

    float z = 0.f;
    for (int t = tid; t < NT; t += 256) z += expf(s[t] - m);
    sm[tid] = z;
    __syncthreads();
    for (int off = 128; off > 0; off >>= 1) {
        if (tid < off) sm[tid] += sm[tid + off];
        __syncthreads();
    }
    float inv = 1.f / sm[0];

    float* w = wout + (size_t)b * NT;
    for (int t = tid; t < NT; t += 256) w[t] = expf(s[t] - m) * inv;
}

// ---------------------------------------------------------------------------
// Kernel 4: context partial sums, float4 vectorized (128 threads / block)
// ---------------------------------------------------------------------------
__global__ void k_ctx_part(const float* __restrict__ enc,
                           const float* __restrict__ w) {
    const int b   = blockIdx.x;
    const int tc  = blockIdx.y;
    const int tid = threadIdx.x;   // 0..127, one float4 column each
    const int TLEN = NT / TCH;     // 128
    const float*  wp = w + (size_t)b * NT + (size_t)tc * TLEN;
    const float4* ep = (const float4*)(enc + ((size_t)b * NT + (size_t)tc * TLEN) * HE);
    float4 acc = make_float4(0.f, 0.f, 0.f, 0.f);
#pragma unroll 4
    for (int t = 0; t < TLEN; ++t) {
        float wt = wp[t];
        float4 e = ep[(size_t)t * (HE / 4) + tid];
        acc.x = fmaf(wt, e.x, acc.x);
        acc.y = fmaf(wt, e.y, acc.y);
        acc.z = fmaf(wt, e.z, acc.z);
        acc.w = fmaf(wt, e.w, acc.w);
    }
    ((float4*)(g_ctx_part + ((size_t)b * TCH + tc) * HE))[tid] = acc;
}

// ---------------------------------------------------------------------------
// Kernel 5: reduce partials -> context output.
// ---------------------------------------------------------------------------
__global__ void k_ctx_reduce(float* __restrict__ ctx) {
    int idx = blockIdx.x * blockDim.x + threadIdx.x;
    int b = idx / HE;
    int e = idx % HE;
    float s = 0.f;
#pragma unroll
    for (int c = 0; c < TCH; c++)
        s += g_ctx_part[((size_t)b * TCH + c) * HE + e];
    ctx[idx] = s;
}

// ---------------------------------------------------------------------------
extern "C" void kernel_launch(void* const* d_in, const int* in_sizes, int n_in,
                              void* d_out, int out_size) {
    const float* dec = (const float*)d_in[0];  // (B, H_dec)
    const float* enc = (const float*)d_in[1];  // (B, T, H_enc)
    const float* We  = (const float*)d_in[2];  // (A, H_enc)
    const float* Wd  = (const float*)d_in[3];  // (A, H_dec)
    const float* v   = (const float*)d_in[4];  // (1, A)

    float* out = (float*)d_out;
    float* ctx = out;              // context: B*HE
    float* wts = out + NB * HE;    // attn_weights: B*NT

    cudaFuncSetAttribute(k_scores, cudaFuncAttributeMaxDynamicSharedMemorySize,
                         SMEM_BYTES);

    k_wprep<<<NKCH, BN>>>(We);
    k_dec_proj<<<NB, NA>>>(dec, Wd);

    dim3 g2(NT / BM, NB);
    k_scores<<<g2, THREADS, SMEM_BYTES>>>(enc, v);

    k_softmax<<<NB, 256>>>(wts);

    dim3 g4(NB, TCH);
    k_ctx_part<<<g4, 128>>>(enc, wts);

    k_ctx_reduce<<<(NB * HE) / 256, 256>>>(ctx);
}